// round 14
// baseline (speedup 1.0000x reference)
#include <cuda_runtime.h>
#include <cstdint>

#define NN 50000
#define HH 64
#define EE 800000
#define MM (2 * NN)
#define SCAN_BLK 1024
#define NB ((MM + SCAN_BLK - 1) / SCAN_BLK)   // 98

// Scratch
__device__ float g_acc[2 * NN * HH];   // a1 | a2
__device__ float g_h[NN * HH];         // intermediate h
__device__ int   g_cnt[MM];
__device__ int   g_ofs[MM + 1];
__device__ int   g_rank[2 * EE];       // per-edge rank within its bin
__device__ int   g_part[NB + 1];
__device__ int2  g_sorted[2 * EE];

// ---------------------------------------------------------------------------
// CSR build: hist (captures per-edge rank) -> scan -> rank-based fill
// ---------------------------------------------------------------------------
__global__ void hist_kernel(const int* __restrict__ dst1,
                            const int* __restrict__ dst2,
                            int* __restrict__ cnt,
                            int* __restrict__ rank, int E, int N) {
    int i = blockIdx.x * blockDim.x + threadIdx.x;
    if (i < E)          rank[i] = atomicAdd(&cnt[dst1[i]], 1);
    else if (i < 2 * E) rank[i] = atomicAdd(&cnt[N + dst2[i - E]], 1);
}

__global__ void scan_partial_kernel(const int* __restrict__ cnt,
                                    int* __restrict__ partial, int M) {
    __shared__ int sdata[SCAN_BLK];
    int i = blockIdx.x * SCAN_BLK + threadIdx.x;
    sdata[threadIdx.x] = (i < M) ? cnt[i] : 0;
    __syncthreads();
    for (int s = SCAN_BLK / 2; s > 0; s >>= 1) {
        if (threadIdx.x < s) sdata[threadIdx.x] += sdata[threadIdx.x + s];
        __syncthreads();
    }
    if (threadIdx.x == 0) partial[blockIdx.x] = sdata[0];
}

__global__ void scan_final_kernel(const int* __restrict__ cnt,
                                  const int* __restrict__ partial,
                                  int* __restrict__ ofs,
                                  int M, int total, int nb) {
    __shared__ int pscan[128];
    __shared__ int sdata[SCAN_BLK];

    if (threadIdx.x < 128)
        pscan[threadIdx.x] = (threadIdx.x < nb) ? partial[threadIdx.x] : 0;
    __syncthreads();
    for (int s = 1; s < 128; s <<= 1) {
        int t = 0;
        if (threadIdx.x < 128 && threadIdx.x >= s) t = pscan[threadIdx.x - s];
        __syncthreads();
        if (threadIdx.x < 128) pscan[threadIdx.x] += t;
        __syncthreads();
    }
    int block_prefix = (blockIdx.x == 0) ? 0 : pscan[blockIdx.x - 1];

    int i = blockIdx.x * SCAN_BLK + threadIdx.x;
    int v = (i < M) ? cnt[i] : 0;
    sdata[threadIdx.x] = v;
    __syncthreads();
    for (int s = 1; s < SCAN_BLK; s <<= 1) {
        int t = (threadIdx.x >= s) ? sdata[threadIdx.x - s] : 0;
        __syncthreads();
        sdata[threadIdx.x] += t;
        __syncthreads();
    }
    int excl = sdata[threadIdx.x] - v + block_prefix;
    if (i < M) ofs[i] = excl;
    if (i == M - 1) ofs[M] = total;
}

__global__ void fill_kernel(const int* __restrict__ src1,
                            const int* __restrict__ dst1,
                            const int* __restrict__ src2,
                            const int* __restrict__ dst2,
                            const int* __restrict__ ofs,
                            const int* __restrict__ rank,
                            int2* __restrict__ sorted, int E, int N) {
    int i = blockIdx.x * blockDim.x + threadIdx.x;
    int e, s, bin;
    if (i < E) {
        e = i; bin = dst1[e]; s = src1[e];
    } else if (i < 2 * E) {
        e = i - E; bin = N + dst2[e]; s = src2[e];
    } else return;
    sorted[ofs[bin] + rank[i]] = make_int2(e, s);
}

// ---------------------------------------------------------------------------
// Gather-aggregate: one warp per (rel, node) bin. 4 edges per warp-step
// (8 lanes x 8 contiguous fp32 per edge). feat via __ldcs; h L2-resident.
// __launch_bounds__(256, 7): cap regs (~36) -> 7 blocks/SM resident.
// (R13: minblocks=6/42regs gave occ win 287.5->275.2; probing one notch.)
// ---------------------------------------------------------------------------
#define FMA4(acc, f, hv)                         \
    acc.x = fmaf(f.x, hv.x, acc.x);              \
    acc.y = fmaf(f.y, hv.y, acc.y);              \
    acc.z = fmaf(f.z, hv.z, acc.z);              \
    acc.w = fmaf(f.w, hv.w, acc.w);

__global__ __launch_bounds__(256, 7)
void gather_kernel(const float* __restrict__ h,
                   const float* __restrict__ feat1,
                   const float* __restrict__ feat2,
                   const int* __restrict__ ofs,
                   const int2* __restrict__ sorted,
                   float* __restrict__ acc_out,
                   int N) {
    int warp = blockIdx.x * (blockDim.x >> 5) + (threadIdx.x >> 5);
    if (warp >= 2 * N) return;

    const float* feat = (warp < N) ? feat1 : feat2;
    const int lane = threadIdx.x & 31;
    const int eg   = lane >> 3;   // edge subgroup 0..3
    const int k8   = lane & 7;    // owns floats [k8*8, k8*8+8)

    const int start = ofs[warp];
    const int end   = ofs[warp + 1];

    float4 acc0 = make_float4(0.f, 0.f, 0.f, 0.f);
    float4 acc1 = make_float4(0.f, 0.f, 0.f, 0.f);

    for (int bs = start; bs < end; bs += 32) {
        int nb = min(32, end - bs);
        int2 es = make_int2(0, 0);
        if (lane < nb) es = sorted[bs + lane];

        #pragma unroll 2
        for (int j4 = 0; j4 < nb; j4 += 4) {
            int j  = j4 + eg;
            int jc = min(j, nb - 1);
            int e  = __shfl_sync(0xffffffffu, es.x, jc);
            int s  = __shfl_sync(0xffffffffu, es.y, jc);
            const float4* fp = (const float4*)(feat + (size_t)e * HH);
            const float4* hp = (const float4*)(h    + (size_t)s * HH);
            float4 f0 = __ldcs(fp + 2 * k8);
            float4 f1 = __ldcs(fp + 2 * k8 + 1);
            float4 h0 = hp[2 * k8];
            float4 h1 = hp[2 * k8 + 1];
            if (j < nb) {
                FMA4(acc0, f0, h0);
                FMA4(acc1, f1, h1);
            }
        }
    }

    // Reduce the 4 edge subgroups (same k8) onto lanes 0..7
    #pragma unroll
    for (int off = 16; off >= 8; off >>= 1) {
        acc0.x += __shfl_down_sync(0xffffffffu, acc0.x, off);
        acc0.y += __shfl_down_sync(0xffffffffu, acc0.y, off);
        acc0.z += __shfl_down_sync(0xffffffffu, acc0.z, off);
        acc0.w += __shfl_down_sync(0xffffffffu, acc0.w, off);
        acc1.x += __shfl_down_sync(0xffffffffu, acc1.x, off);
        acc1.y += __shfl_down_sync(0xffffffffu, acc1.y, off);
        acc1.z += __shfl_down_sync(0xffffffffu, acc1.z, off);
        acc1.w += __shfl_down_sync(0xffffffffu, acc1.w, off);
    }

    if (lane < 8) {
        float4* op = (float4*)(acc_out + (size_t)warp * HH);
        op[2 * k8]     = acc0;
        op[2 * k8 + 1] = acc1;
    }
}

// ---------------------------------------------------------------------------
// Update: h_out = h_in + relu(concat(a1,a2) @ W + b)
// Register-tiled 64x64 block, 4 nodes x 4 cols (float4) per thread.
// [Frozen R5/R10/R13 configuration]
// ---------------------------------------------------------------------------
#define APAD 132
#define UPD_SMEM_BYTES ((128 * 64 + 64 * APAD) * 4)

__global__ void update_kernel(const float* __restrict__ h_in,
                              const float* __restrict__ a1,
                              const float* __restrict__ a2,
                              const float* __restrict__ W,
                              const float* __restrict__ b,
                              float* __restrict__ h_out,
                              int N) {
    extern __shared__ float smem[];
    float* Ws = smem;
    float (*As)[APAD] = (float (*)[APAD])(smem + 128 * 64);

    const int tid = threadIdx.x;
    const int tc  = tid & 15;
    const int tn  = tid >> 4;

    for (int i = tid; i < 128 * 16; i += 256)
        ((float4*)Ws)[i] = ((const float4*)W)[i];

    const float4 bias = ((const float4*)b)[tc];
    const int base = blockIdx.x * 64;

    for (int i = tid; i < 2048; i += 256) {
        int node = i >> 5;
        int kq   = i & 31;
        int gn   = base + node;
        float4 v = make_float4(0.f, 0.f, 0.f, 0.f);
        if (gn < N) {
            if (kq < 16) v = ((const float4*)(a1 + (size_t)gn * HH))[kq];
            else         v = ((const float4*)(a2 + (size_t)gn * HH))[kq - 16];
        }
        *(float4*)&As[node][kq * 4] = v;
    }
    __syncthreads();

    float4 acc[4];
    #pragma unroll
    for (int i = 0; i < 4; i++) acc[i] = bias;

    #pragma unroll 4
    for (int k4 = 0; k4 < 32; k4++) {
        const int k = k4 * 4;
        float4 w0 = *(const float4*)&Ws[(k + 0) * 64 + tc * 4];
        float4 w1 = *(const float4*)&Ws[(k + 1) * 64 + tc * 4];
        float4 w2 = *(const float4*)&Ws[(k + 2) * 64 + tc * 4];
        float4 w3 = *(const float4*)&Ws[(k + 3) * 64 + tc * 4];
        #pragma unroll
        for (int i = 0; i < 4; i++) {
            float4 a = *(const float4*)&As[tn * 4 + i][k];
            acc[i].x = fmaf(a.w, w3.x, fmaf(a.z, w2.x, fmaf(a.y, w1.x, fmaf(a.x, w0.x, acc[i].x))));
            acc[i].y = fmaf(a.w, w3.y, fmaf(a.z, w2.y, fmaf(a.y, w1.y, fmaf(a.x, w0.y, acc[i].y))));
            acc[i].z = fmaf(a.w, w3.z, fmaf(a.z, w2.z, fmaf(a.y, w1.z, fmaf(a.x, w0.z, acc[i].z))));
            acc[i].w = fmaf(a.w, w3.w, fmaf(a.z, w2.w, fmaf(a.y, w1.w, fmaf(a.x, w0.w, acc[i].w))));
        }
    }

    #pragma unroll
    for (int i = 0; i < 4; i++) {
        int gn = base + tn * 4 + i;
        if (gn < N) {
            float4 hv = ((const float4*)(h_in + (size_t)gn * HH))[tc];
            float4 o;
            o.x = hv.x + fmaxf(acc[i].x, 0.f);
            o.y = hv.y + fmaxf(acc[i].y, 0.f);
            o.z = hv.z + fmaxf(acc[i].z, 0.f);
            o.w = hv.w + fmaxf(acc[i].w, 0.f);
            ((float4*)(h_out + (size_t)gn * HH))[tc] = o;
        }
    }
}

// ---------------------------------------------------------------------------
// Launch
// ---------------------------------------------------------------------------
extern "C" void kernel_launch(void* const* d_in, const int* in_sizes, int n_in,
                              void* d_out, int out_size) {
    const float* h0    = (const float*)d_in[0];
    const float* feat1 = (const float*)d_in[1];
    const float* feat2 = (const float*)d_in[2];
    const float* W1    = (const float*)d_in[3];
    const float* b1    = (const float*)d_in[4];
    const float* W2    = (const float*)d_in[5];
    const float* b2    = (const float*)d_in[6];
    const int*   src1  = (const int*)d_in[7];
    const int*   dst1  = (const int*)d_in[8];
    const int*   src2  = (const int*)d_in[9];
    const int*   dst2  = (const int*)d_in[10];
    float* out = (float*)d_out;

    const int N = in_sizes[0] / HH;
    const int E = in_sizes[7];
    const int M = 2 * N;

    float* acc_base; float* hbuf;
    int *cnt, *ofs, *rank, *part; int2* sorted;
    cudaGetSymbolAddress((void**)&acc_base, g_acc);
    cudaGetSymbolAddress((void**)&hbuf, g_h);
    cudaGetSymbolAddress((void**)&cnt, g_cnt);
    cudaGetSymbolAddress((void**)&ofs, g_ofs);
    cudaGetSymbolAddress((void**)&rank, g_rank);
    cudaGetSymbolAddress((void**)&part, g_part);
    cudaGetSymbolAddress((void**)&sorted, g_sorted);
    float* a1 = acc_base;
    float* a2 = acc_base + (size_t)N * HH;

    static bool attr_set = false;
    if (!attr_set) {
        cudaFuncSetAttribute(update_kernel,
                             cudaFuncAttributeMaxDynamicSharedMemorySize,
                             UPD_SMEM_BYTES);
        attr_set = true;
    }

    // ---- CSR build (once; shared by both layers) ----
    cudaMemsetAsync(cnt, 0, (size_t)M * sizeof(int));
    hist_kernel<<<(2 * E + 255) / 256, 256>>>(dst1, dst2, cnt, rank, E, N);
    const int nb = (M + SCAN_BLK - 1) / SCAN_BLK;
    scan_partial_kernel<<<nb, SCAN_BLK>>>(cnt, part, M);
    scan_final_kernel<<<nb, SCAN_BLK>>>(cnt, part, ofs, M, 2 * E, nb);
    fill_kernel<<<(2 * E + 255) / 256, 256>>>(src1, dst1, src2, dst2, ofs,
                                              rank, sorted, E, N);

    const int ggrid = (M * 32 + 255) / 256;
    const int ugrid = (N + 63) / 64;

    // ---- Layer 1 ----
    gather_kernel<<<ggrid, 256>>>(h0, feat1, feat2, ofs, sorted, acc_base, N);
    update_kernel<<<ugrid, 256, UPD_SMEM_BYTES>>>(h0, a1, a2, W1, b1, hbuf, N);

    // ---- Layer 2 ----
    gather_kernel<<<ggrid, 256>>>(hbuf, feat1, feat2, ofs, sorted, acc_base, N);
    update_kernel<<<ugrid, 256, UPD_SMEM_BYTES>>>(hbuf, a1, a2, W2, b2, out, N);
}

// round 15
// speedup vs baseline: 1.0524x; 1.0524x over previous
#include <cuda_runtime.h>
#include <cstdint>

#define NN 50000
#define HH 64
#define EE 800000
#define MM (2 * NN)
#define SCAN_BLK 1024
#define NB ((MM + SCAN_BLK - 1) / SCAN_BLK)   // 98

// Scratch
__device__ float g_acc[2 * NN * HH];   // a1 | a2
__device__ float g_h[NN * HH];         // intermediate h
__device__ int   g_cnt[MM];
__device__ int   g_ofs[MM + 1];
__device__ int   g_rank[2 * EE];       // per-edge rank within its bin
__device__ int   g_part[NB + 1];
__device__ int2  g_sorted[2 * EE];

// ---------------------------------------------------------------------------
// CSR build: hist (captures per-edge rank) -> scan -> rank-based fill
// ---------------------------------------------------------------------------
__global__ void hist_kernel(const int* __restrict__ dst1,
                            const int* __restrict__ dst2,
                            int* __restrict__ cnt,
                            int* __restrict__ rank, int E, int N) {
    int i = blockIdx.x * blockDim.x + threadIdx.x;
    if (i < E)          rank[i] = atomicAdd(&cnt[dst1[i]], 1);
    else if (i < 2 * E) rank[i] = atomicAdd(&cnt[N + dst2[i - E]], 1);
}

__global__ void scan_partial_kernel(const int* __restrict__ cnt,
                                    int* __restrict__ partial, int M) {
    __shared__ int sdata[SCAN_BLK];
    int i = blockIdx.x * SCAN_BLK + threadIdx.x;
    sdata[threadIdx.x] = (i < M) ? cnt[i] : 0;
    __syncthreads();
    for (int s = SCAN_BLK / 2; s > 0; s >>= 1) {
        if (threadIdx.x < s) sdata[threadIdx.x] += sdata[threadIdx.x + s];
        __syncthreads();
    }
    if (threadIdx.x == 0) partial[blockIdx.x] = sdata[0];
}

__global__ void scan_final_kernel(const int* __restrict__ cnt,
                                  const int* __restrict__ partial,
                                  int* __restrict__ ofs,
                                  int M, int total, int nb) {
    __shared__ int pscan[128];
    __shared__ int sdata[SCAN_BLK];

    if (threadIdx.x < 128)
        pscan[threadIdx.x] = (threadIdx.x < nb) ? partial[threadIdx.x] : 0;
    __syncthreads();
    for (int s = 1; s < 128; s <<= 1) {
        int t = 0;
        if (threadIdx.x < 128 && threadIdx.x >= s) t = pscan[threadIdx.x - s];
        __syncthreads();
        if (threadIdx.x < 128) pscan[threadIdx.x] += t;
        __syncthreads();
    }
    int block_prefix = (blockIdx.x == 0) ? 0 : pscan[blockIdx.x - 1];

    int i = blockIdx.x * SCAN_BLK + threadIdx.x;
    int v = (i < M) ? cnt[i] : 0;
    sdata[threadIdx.x] = v;
    __syncthreads();
    for (int s = 1; s < SCAN_BLK; s <<= 1) {
        int t = (threadIdx.x >= s) ? sdata[threadIdx.x - s] : 0;
        __syncthreads();
        sdata[threadIdx.x] += t;
        __syncthreads();
    }
    int excl = sdata[threadIdx.x] - v + block_prefix;
    if (i < M) ofs[i] = excl;
    if (i == M - 1) ofs[M] = total;
}

__global__ void fill_kernel(const int* __restrict__ src1,
                            const int* __restrict__ dst1,
                            const int* __restrict__ src2,
                            const int* __restrict__ dst2,
                            const int* __restrict__ ofs,
                            const int* __restrict__ rank,
                            int2* __restrict__ sorted, int E, int N) {
    int i = blockIdx.x * blockDim.x + threadIdx.x;
    int e, s, bin;
    if (i < E) {
        e = i; bin = dst1[e]; s = src1[e];
    } else if (i < 2 * E) {
        e = i - E; bin = N + dst2[e]; s = src2[e];
    } else return;
    sorted[ofs[bin] + rank[i]] = make_int2(e, s);
}

// ---------------------------------------------------------------------------
// Gather-aggregate: one warp per (rel, node) bin. 4 edges per warp-step
// (8 lanes x 8 contiguous fp32 per edge). feat via __ldcs; h L2-resident.
// __launch_bounds__(256, 6): FROZEN — measured best (R13, 275.2us total;
// minblocks=7 spills and regresses).
// ---------------------------------------------------------------------------
#define FMA4(acc, f, hv)                         \
    acc.x = fmaf(f.x, hv.x, acc.x);              \
    acc.y = fmaf(f.y, hv.y, acc.y);              \
    acc.z = fmaf(f.z, hv.z, acc.z);              \
    acc.w = fmaf(f.w, hv.w, acc.w);

__global__ __launch_bounds__(256, 6)
void gather_kernel(const float* __restrict__ h,
                   const float* __restrict__ feat1,
                   const float* __restrict__ feat2,
                   const int* __restrict__ ofs,
                   const int2* __restrict__ sorted,
                   float* __restrict__ acc_out,
                   int N) {
    int warp = blockIdx.x * (blockDim.x >> 5) + (threadIdx.x >> 5);
    if (warp >= 2 * N) return;

    const float* feat = (warp < N) ? feat1 : feat2;
    const int lane = threadIdx.x & 31;
    const int eg   = lane >> 3;   // edge subgroup 0..3
    const int k8   = lane & 7;    // owns floats [k8*8, k8*8+8)

    const int start = ofs[warp];
    const int end   = ofs[warp + 1];

    float4 acc0 = make_float4(0.f, 0.f, 0.f, 0.f);
    float4 acc1 = make_float4(0.f, 0.f, 0.f, 0.f);

    for (int bs = start; bs < end; bs += 32) {
        int nb = min(32, end - bs);
        int2 es = make_int2(0, 0);
        if (lane < nb) es = sorted[bs + lane];

        #pragma unroll 2
        for (int j4 = 0; j4 < nb; j4 += 4) {
            int j  = j4 + eg;
            int jc = min(j, nb - 1);
            int e  = __shfl_sync(0xffffffffu, es.x, jc);
            int s  = __shfl_sync(0xffffffffu, es.y, jc);
            const float4* fp = (const float4*)(feat + (size_t)e * HH);
            const float4* hp = (const float4*)(h    + (size_t)s * HH);
            float4 f0 = __ldcs(fp + 2 * k8);
            float4 f1 = __ldcs(fp + 2 * k8 + 1);
            float4 h0 = hp[2 * k8];
            float4 h1 = hp[2 * k8 + 1];
            if (j < nb) {
                FMA4(acc0, f0, h0);
                FMA4(acc1, f1, h1);
            }
        }
    }

    // Reduce the 4 edge subgroups (same k8) onto lanes 0..7
    #pragma unroll
    for (int off = 16; off >= 8; off >>= 1) {
        acc0.x += __shfl_down_sync(0xffffffffu, acc0.x, off);
        acc0.y += __shfl_down_sync(0xffffffffu, acc0.y, off);
        acc0.z += __shfl_down_sync(0xffffffffu, acc0.z, off);
        acc0.w += __shfl_down_sync(0xffffffffu, acc0.w, off);
        acc1.x += __shfl_down_sync(0xffffffffu, acc1.x, off);
        acc1.y += __shfl_down_sync(0xffffffffu, acc1.y, off);
        acc1.z += __shfl_down_sync(0xffffffffu, acc1.z, off);
        acc1.w += __shfl_down_sync(0xffffffffu, acc1.w, off);
    }

    if (lane < 8) {
        float4* op = (float4*)(acc_out + (size_t)warp * HH);
        op[2 * k8]     = acc0;
        op[2 * k8 + 1] = acc1;
    }
}

// ---------------------------------------------------------------------------
// Update: h_out = h_in + relu(concat(a1,a2) @ W + b)
// Re-tiled: 128 nodes x 64 cols per block, 8 nodes x 4 cols per thread.
// LDS per k4-step: 4 W-loads + 8 A-loads serve 128 FMAs (1.5 B/FMA, was 2).
// smem = 32KB (W) + 67.6KB (As) -> 2 blocks/SM.
// ---------------------------------------------------------------------------
#define APAD 132
#define UPD_SMEM_BYTES ((128 * 64 + 128 * APAD) * 4)

__global__ __launch_bounds__(256)
void update_kernel(const float* __restrict__ h_in,
                   const float* __restrict__ a1,
                   const float* __restrict__ a2,
                   const float* __restrict__ W,
                   const float* __restrict__ b,
                   float* __restrict__ h_out,
                   int N) {
    extern __shared__ float smem[];
    float* Ws = smem;                                        // [128][64]
    float (*As)[APAD] = (float (*)[APAD])(smem + 128 * 64);  // [128][APAD]

    const int tid = threadIdx.x;
    const int tc  = tid & 15;   // col group: cols 4*tc..4*tc+3
    const int tn  = tid >> 4;   // node group: nodes 8*tn..8*tn+7

    for (int i = tid; i < 128 * 16; i += 256)
        ((float4*)Ws)[i] = ((const float4*)W)[i];

    const float4 bias = ((const float4*)b)[tc];
    const int base = blockIdx.x * 128;

    // Load A-tile: 128 nodes x 128 k  (4096 float4, 16 per thread)
    for (int i = tid; i < 4096; i += 256) {
        int node = i >> 5;
        int kq   = i & 31;
        int gn   = base + node;
        float4 v = make_float4(0.f, 0.f, 0.f, 0.f);
        if (gn < N) {
            if (kq < 16) v = ((const float4*)(a1 + (size_t)gn * HH))[kq];
            else         v = ((const float4*)(a2 + (size_t)gn * HH))[kq - 16];
        }
        *(float4*)&As[node][kq * 4] = v;
    }
    __syncthreads();

    float4 acc[8];
    #pragma unroll
    for (int i = 0; i < 8; i++) acc[i] = bias;

    #pragma unroll 2
    for (int k4 = 0; k4 < 32; k4++) {
        const int k = k4 * 4;
        float4 w0 = *(const float4*)&Ws[(k + 0) * 64 + tc * 4];
        float4 w1 = *(const float4*)&Ws[(k + 1) * 64 + tc * 4];
        float4 w2 = *(const float4*)&Ws[(k + 2) * 64 + tc * 4];
        float4 w3 = *(const float4*)&Ws[(k + 3) * 64 + tc * 4];
        #pragma unroll
        for (int i = 0; i < 8; i++) {
            float4 a = *(const float4*)&As[tn * 8 + i][k];
            acc[i].x = fmaf(a.w, w3.x, fmaf(a.z, w2.x, fmaf(a.y, w1.x, fmaf(a.x, w0.x, acc[i].x))));
            acc[i].y = fmaf(a.w, w3.y, fmaf(a.z, w2.y, fmaf(a.y, w1.y, fmaf(a.x, w0.y, acc[i].y))));
            acc[i].z = fmaf(a.w, w3.z, fmaf(a.z, w2.z, fmaf(a.y, w1.z, fmaf(a.x, w0.z, acc[i].z))));
            acc[i].w = fmaf(a.w, w3.w, fmaf(a.z, w2.w, fmaf(a.y, w1.w, fmaf(a.x, w0.w, acc[i].w))));
        }
    }

    #pragma unroll
    for (int i = 0; i < 8; i++) {
        int gn = base + tn * 8 + i;
        if (gn < N) {
            float4 hv = ((const float4*)(h_in + (size_t)gn * HH))[tc];
            float4 o;
            o.x = hv.x + fmaxf(acc[i].x, 0.f);
            o.y = hv.y + fmaxf(acc[i].y, 0.f);
            o.z = hv.z + fmaxf(acc[i].z, 0.f);
            o.w = hv.w + fmaxf(acc[i].w, 0.f);
            ((float4*)(h_out + (size_t)gn * HH))[tc] = o;
        }
    }
}

// ---------------------------------------------------------------------------
// Launch
// ---------------------------------------------------------------------------
extern "C" void kernel_launch(void* const* d_in, const int* in_sizes, int n_in,
                              void* d_out, int out_size) {
    const float* h0    = (const float*)d_in[0];
    const float* feat1 = (const float*)d_in[1];
    const float* feat2 = (const float*)d_in[2];
    const float* W1    = (const float*)d_in[3];
    const float* b1    = (const float*)d_in[4];
    const float* W2    = (const float*)d_in[5];
    const float* b2    = (const float*)d_in[6];
    const int*   src1  = (const int*)d_in[7];
    const int*   dst1  = (const int*)d_in[8];
    const int*   src2  = (const int*)d_in[9];
    const int*   dst2  = (const int*)d_in[10];
    float* out = (float*)d_out;

    const int N = in_sizes[0] / HH;
    const int E = in_sizes[7];
    const int M = 2 * N;

    float* acc_base; float* hbuf;
    int *cnt, *ofs, *rank, *part; int2* sorted;
    cudaGetSymbolAddress((void**)&acc_base, g_acc);
    cudaGetSymbolAddress((void**)&hbuf, g_h);
    cudaGetSymbolAddress((void**)&cnt, g_cnt);
    cudaGetSymbolAddress((void**)&ofs, g_ofs);
    cudaGetSymbolAddress((void**)&rank, g_rank);
    cudaGetSymbolAddress((void**)&part, g_part);
    cudaGetSymbolAddress((void**)&sorted, g_sorted);
    float* a1 = acc_base;
    float* a2 = acc_base + (size_t)N * HH;

    static bool attr_set = false;
    if (!attr_set) {
        cudaFuncSetAttribute(update_kernel,
                             cudaFuncAttributeMaxDynamicSharedMemorySize,
                             UPD_SMEM_BYTES);
        attr_set = true;
    }

    // ---- CSR build (once; shared by both layers) ----
    cudaMemsetAsync(cnt, 0, (size_t)M * sizeof(int));
    hist_kernel<<<(2 * E + 255) / 256, 256>>>(dst1, dst2, cnt, rank, E, N);
    const int nb = (M + SCAN_BLK - 1) / SCAN_BLK;
    scan_partial_kernel<<<nb, SCAN_BLK>>>(cnt, part, M);
    scan_final_kernel<<<nb, SCAN_BLK>>>(cnt, part, ofs, M, 2 * E, nb);
    fill_kernel<<<(2 * E + 255) / 256, 256>>>(src1, dst1, src2, dst2, ofs,
                                              rank, sorted, E, N);

    const int ggrid = (M * 32 + 255) / 256;
    const int ugrid = (N + 127) / 128;

    // ---- Layer 1 ----
    gather_kernel<<<ggrid, 256>>>(h0, feat1, feat2, ofs, sorted, acc_base, N);
    update_kernel<<<ugrid, 256, UPD_SMEM_BYTES>>>(h0, a1, a2, W1, b1, hbuf, N);

    // ---- Layer 2 ----
    gather_kernel<<<ggrid, 256>>>(hbuf, feat1, feat2, ofs, sorted, acc_base, N);
    update_kernel<<<ugrid, 256, UPD_SMEM_BYTES>>>(hbuf, a1, a2, W2, b2, out, N);
}

// round 16
// speedup vs baseline: 1.0700x; 1.0167x over previous
#include <cuda_runtime.h>
#include <cstdint>

#define NN 50000
#define HH 64
#define EE 800000
#define MM (2 * NN)
#define SCAN_BLK 1024
#define NB ((MM + SCAN_BLK - 1) / SCAN_BLK)   // 98

// Scratch
__device__ float g_acc[2 * NN * HH];   // a1 | a2
__device__ float g_h[NN * HH];         // intermediate h
__device__ int   g_cnt[MM];
__device__ int   g_ofs[MM + 1];
__device__ int   g_rank[2 * EE];       // per-edge rank within its bin
__device__ int   g_part[NB + 1];
__device__ int2  g_sorted[2 * EE];

// ---------------------------------------------------------------------------
// CSR build: hist (captures per-edge rank) -> scan -> rank-based fill
// ---------------------------------------------------------------------------
__global__ void hist_kernel(const int* __restrict__ dst1,
                            const int* __restrict__ dst2,
                            int* __restrict__ cnt,
                            int* __restrict__ rank, int E, int N) {
    int i = blockIdx.x * blockDim.x + threadIdx.x;
    if (i < E)          rank[i] = atomicAdd(&cnt[dst1[i]], 1);
    else if (i < 2 * E) rank[i] = atomicAdd(&cnt[N + dst2[i - E]], 1);
}

__global__ void scan_partial_kernel(const int* __restrict__ cnt,
                                    int* __restrict__ partial, int M) {
    __shared__ int sdata[SCAN_BLK];
    int i = blockIdx.x * SCAN_BLK + threadIdx.x;
    sdata[threadIdx.x] = (i < M) ? cnt[i] : 0;
    __syncthreads();
    for (int s = SCAN_BLK / 2; s > 0; s >>= 1) {
        if (threadIdx.x < s) sdata[threadIdx.x] += sdata[threadIdx.x + s];
        __syncthreads();
    }
    if (threadIdx.x == 0) partial[blockIdx.x] = sdata[0];
}

__global__ void scan_final_kernel(const int* __restrict__ cnt,
                                  const int* __restrict__ partial,
                                  int* __restrict__ ofs,
                                  int M, int total, int nb) {
    __shared__ int pscan[128];
    __shared__ int sdata[SCAN_BLK];

    if (threadIdx.x < 128)
        pscan[threadIdx.x] = (threadIdx.x < nb) ? partial[threadIdx.x] : 0;
    __syncthreads();
    for (int s = 1; s < 128; s <<= 1) {
        int t = 0;
        if (threadIdx.x < 128 && threadIdx.x >= s) t = pscan[threadIdx.x - s];
        __syncthreads();
        if (threadIdx.x < 128) pscan[threadIdx.x] += t;
        __syncthreads();
    }
    int block_prefix = (blockIdx.x == 0) ? 0 : pscan[blockIdx.x - 1];

    int i = blockIdx.x * SCAN_BLK + threadIdx.x;
    int v = (i < M) ? cnt[i] : 0;
    sdata[threadIdx.x] = v;
    __syncthreads();
    for (int s = 1; s < SCAN_BLK; s <<= 1) {
        int t = (threadIdx.x >= s) ? sdata[threadIdx.x - s] : 0;
        __syncthreads();
        sdata[threadIdx.x] += t;
        __syncthreads();
    }
    int excl = sdata[threadIdx.x] - v + block_prefix;
    if (i < M) ofs[i] = excl;
    if (i == M - 1) ofs[M] = total;
}

// Fill, 4 edges per thread (int4 vector loads of dst/src/rank -> MLP=4 per
// thread; fill was measured latency-bound: 17.4us, issue 9.5%, DRAM 14%).
// Requires E % 4 == 0 (E=800000). Same positions/contents as scalar version.
__global__ void fill_kernel(const int* __restrict__ src1,
                            const int* __restrict__ dst1,
                            const int* __restrict__ src2,
                            const int* __restrict__ dst2,
                            const int* __restrict__ ofs,
                            const int* __restrict__ rank,
                            int2* __restrict__ sorted, int E, int N) {
    int t = blockIdx.x * blockDim.x + threadIdx.x;
    const int E4 = E >> 2;
    if (t >= 2 * E4) return;

    int e0, binofs, rk0;
    const int* src;
    const int* dst;
    if (t < E4) {
        e0 = t * 4;  src = src1; dst = dst1; binofs = 0; rk0 = e0;
    } else {
        e0 = (t - E4) * 4; src = src2; dst = dst2; binofs = N; rk0 = E + e0;
    }

    int4 d = *(const int4*)(dst  + e0);
    int4 s = *(const int4*)(src  + e0);
    int4 r = *(const int4*)(rank + rk0);

    sorted[ofs[binofs + d.x] + r.x] = make_int2(e0 + 0, s.x);
    sorted[ofs[binofs + d.y] + r.y] = make_int2(e0 + 1, s.y);
    sorted[ofs[binofs + d.z] + r.z] = make_int2(e0 + 2, s.z);
    sorted[ofs[binofs + d.w] + r.w] = make_int2(e0 + 3, s.w);
}

// ---------------------------------------------------------------------------
// Gather-aggregate: one warp per (rel, node) bin. 4 edges per warp-step
// (8 lanes x 8 contiguous fp32 per edge). feat via __ldcs; h L2-resident.
// __launch_bounds__(256, 6): FROZEN — measured best (R13, 275.2us total;
// minblocks=7 spills and regresses, minblocks=5 under-occupies).
// ---------------------------------------------------------------------------
#define FMA4(acc, f, hv)                         \
    acc.x = fmaf(f.x, hv.x, acc.x);              \
    acc.y = fmaf(f.y, hv.y, acc.y);              \
    acc.z = fmaf(f.z, hv.z, acc.z);              \
    acc.w = fmaf(f.w, hv.w, acc.w);

__global__ __launch_bounds__(256, 6)
void gather_kernel(const float* __restrict__ h,
                   const float* __restrict__ feat1,
                   const float* __restrict__ feat2,
                   const int* __restrict__ ofs,
                   const int2* __restrict__ sorted,
                   float* __restrict__ acc_out,
                   int N) {
    int warp = blockIdx.x * (blockDim.x >> 5) + (threadIdx.x >> 5);
    if (warp >= 2 * N) return;

    const float* feat = (warp < N) ? feat1 : feat2;
    const int lane = threadIdx.x & 31;
    const int eg   = lane >> 3;   // edge subgroup 0..3
    const int k8   = lane & 7;    // owns floats [k8*8, k8*8+8)

    const int start = ofs[warp];
    const int end   = ofs[warp + 1];

    float4 acc0 = make_float4(0.f, 0.f, 0.f, 0.f);
    float4 acc1 = make_float4(0.f, 0.f, 0.f, 0.f);

    for (int bs = start; bs < end; bs += 32) {
        int nb = min(32, end - bs);
        int2 es = make_int2(0, 0);
        if (lane < nb) es = sorted[bs + lane];

        #pragma unroll 2
        for (int j4 = 0; j4 < nb; j4 += 4) {
            int j  = j4 + eg;
            int jc = min(j, nb - 1);
            int e  = __shfl_sync(0xffffffffu, es.x, jc);
            int s  = __shfl_sync(0xffffffffu, es.y, jc);
            const float4* fp = (const float4*)(feat + (size_t)e * HH);
            const float4* hp = (const float4*)(h    + (size_t)s * HH);
            float4 f0 = __ldcs(fp + 2 * k8);
            float4 f1 = __ldcs(fp + 2 * k8 + 1);
            float4 h0 = hp[2 * k8];
            float4 h1 = hp[2 * k8 + 1];
            if (j < nb) {
                FMA4(acc0, f0, h0);
                FMA4(acc1, f1, h1);
            }
        }
    }

    // Reduce the 4 edge subgroups (same k8) onto lanes 0..7
    #pragma unroll
    for (int off = 16; off >= 8; off >>= 1) {
        acc0.x += __shfl_down_sync(0xffffffffu, acc0.x, off);
        acc0.y += __shfl_down_sync(0xffffffffu, acc0.y, off);
        acc0.z += __shfl_down_sync(0xffffffffu, acc0.z, off);
        acc0.w += __shfl_down_sync(0xffffffffu, acc0.w, off);
        acc1.x += __shfl_down_sync(0xffffffffu, acc1.x, off);
        acc1.y += __shfl_down_sync(0xffffffffu, acc1.y, off);
        acc1.z += __shfl_down_sync(0xffffffffu, acc1.z, off);
        acc1.w += __shfl_down_sync(0xffffffffu, acc1.w, off);
    }

    if (lane < 8) {
        float4* op = (float4*)(acc_out + (size_t)warp * HH);
        op[2 * k8]     = acc0;
        op[2 * k8 + 1] = acc1;
    }
}

// ---------------------------------------------------------------------------
// Update: h_out = h_in + relu(concat(a1,a2) @ W + b)
// Register-tiled 64x64 block, 4 nodes x 4 cols (float4) per thread.
// FROZEN at R13 config (3 blocks/SM; 128-node re-tile regressed to 2/SM).
// ---------------------------------------------------------------------------
#define APAD 132
#define UPD_SMEM_BYTES ((128 * 64 + 64 * APAD) * 4)

__global__ void update_kernel(const float* __restrict__ h_in,
                              const float* __restrict__ a1,
                              const float* __restrict__ a2,
                              const float* __restrict__ W,
                              const float* __restrict__ b,
                              float* __restrict__ h_out,
                              int N) {
    extern __shared__ float smem[];
    float* Ws = smem;
    float (*As)[APAD] = (float (*)[APAD])(smem + 128 * 64);

    const int tid = threadIdx.x;
    const int tc  = tid & 15;
    const int tn  = tid >> 4;

    for (int i = tid; i < 128 * 16; i += 256)
        ((float4*)Ws)[i] = ((const float4*)W)[i];

    const float4 bias = ((const float4*)b)[tc];
    const int base = blockIdx.x * 64;

    for (int i = tid; i < 2048; i += 256) {
        int node = i >> 5;
        int kq   = i & 31;
        int gn   = base + node;
        float4 v = make_float4(0.f, 0.f, 0.f, 0.f);
        if (gn < N) {
            if (kq < 16) v = ((const float4*)(a1 + (size_t)gn * HH))[kq];
            else         v = ((const float4*)(a2 + (size_t)gn * HH))[kq - 16];
        }
        *(float4*)&As[node][kq * 4] = v;
    }
    __syncthreads();

    float4 acc[4];
    #pragma unroll
    for (int i = 0; i < 4; i++) acc[i] = bias;

    #pragma unroll 4
    for (int k4 = 0; k4 < 32; k4++) {
        const int k = k4 * 4;
        float4 w0 = *(const float4*)&Ws[(k + 0) * 64 + tc * 4];
        float4 w1 = *(const float4*)&Ws[(k + 1) * 64 + tc * 4];
        float4 w2 = *(const float4*)&Ws[(k + 2) * 64 + tc * 4];
        float4 w3 = *(const float4*)&Ws[(k + 3) * 64 + tc * 4];
        #pragma unroll
        for (int i = 0; i < 4; i++) {
            float4 a = *(const float4*)&As[tn * 4 + i][k];
            acc[i].x = fmaf(a.w, w3.x, fmaf(a.z, w2.x, fmaf(a.y, w1.x, fmaf(a.x, w0.x, acc[i].x))));
            acc[i].y = fmaf(a.w, w3.y, fmaf(a.z, w2.y, fmaf(a.y, w1.y, fmaf(a.x, w0.y, acc[i].y))));
            acc[i].z = fmaf(a.w, w3.z, fmaf(a.z, w2.z, fmaf(a.y, w1.z, fmaf(a.x, w0.z, acc[i].z))));
            acc[i].w = fmaf(a.w, w3.w, fmaf(a.z, w2.w, fmaf(a.y, w1.w, fmaf(a.x, w0.w, acc[i].w))));
        }
    }

    #pragma unroll
    for (int i = 0; i < 4; i++) {
        int gn = base + tn * 4 + i;
        if (gn < N) {
            float4 hv = ((const float4*)(h_in + (size_t)gn * HH))[tc];
            float4 o;
            o.x = hv.x + fmaxf(acc[i].x, 0.f);
            o.y = hv.y + fmaxf(acc[i].y, 0.f);
            o.z = hv.z + fmaxf(acc[i].z, 0.f);
            o.w = hv.w + fmaxf(acc[i].w, 0.f);
            ((float4*)(h_out + (size_t)gn * HH))[tc] = o;
        }
    }
}

// ---------------------------------------------------------------------------
// Launch
// ---------------------------------------------------------------------------
extern "C" void kernel_launch(void* const* d_in, const int* in_sizes, int n_in,
                              void* d_out, int out_size) {
    const float* h0    = (const float*)d_in[0];
    const float* feat1 = (const float*)d_in[1];
    const float* feat2 = (const float*)d_in[2];
    const float* W1    = (const float*)d_in[3];
    const float* b1    = (const float*)d_in[4];
    const float* W2    = (const float*)d_in[5];
    const float* b2    = (const float*)d_in[6];
    const int*   src1  = (const int*)d_in[7];
    const int*   dst1  = (const int*)d_in[8];
    const int*   src2  = (const int*)d_in[9];
    const int*   dst2  = (const int*)d_in[10];
    float* out = (float*)d_out;

    const int N = in_sizes[0] / HH;
    const int E = in_sizes[7];
    const int M = 2 * N;

    float* acc_base; float* hbuf;
    int *cnt, *ofs, *rank, *part; int2* sorted;
    cudaGetSymbolAddress((void**)&acc_base, g_acc);
    cudaGetSymbolAddress((void**)&hbuf, g_h);
    cudaGetSymbolAddress((void**)&cnt, g_cnt);
    cudaGetSymbolAddress((void**)&ofs, g_ofs);
    cudaGetSymbolAddress((void**)&rank, g_rank);
    cudaGetSymbolAddress((void**)&part, g_part);
    cudaGetSymbolAddress((void**)&sorted, g_sorted);
    float* a1 = acc_base;
    float* a2 = acc_base + (size_t)N * HH;

    static bool attr_set = false;
    if (!attr_set) {
        cudaFuncSetAttribute(update_kernel,
                             cudaFuncAttributeMaxDynamicSharedMemorySize,
                             UPD_SMEM_BYTES);
        attr_set = true;
    }

    // ---- CSR build (once; shared by both layers) ----
    cudaMemsetAsync(cnt, 0, (size_t)M * sizeof(int));
    hist_kernel<<<(2 * E + 255) / 256, 256>>>(dst1, dst2, cnt, rank, E, N);
    const int nb = (M + SCAN_BLK - 1) / SCAN_BLK;
    scan_partial_kernel<<<nb, SCAN_BLK>>>(cnt, part, M);
    scan_final_kernel<<<nb, SCAN_BLK>>>(cnt, part, ofs, M, 2 * E, nb);
    const int fthreads = 2 * (E >> 2);
    fill_kernel<<<(fthreads + 255) / 256, 256>>>(src1, dst1, src2, dst2, ofs,
                                                 rank, sorted, E, N);

    const int ggrid = (M * 32 + 255) / 256;
    const int ugrid = (N + 63) / 64;

    // ---- Layer 1 ----
    gather_kernel<<<ggrid, 256>>>(h0, feat1, feat2, ofs, sorted, acc_base, N);
    update_kernel<<<ugrid, 256, UPD_SMEM_BYTES>>>(h0, a1, a2, W1, b1, hbuf, N);

    // ---- Layer 2 ----
    gather_kernel<<<ggrid, 256>>>(hbuf, feat1, feat2, ofs, sorted, acc_base, N);
    update_kernel<<<ugrid, 256, UPD_SMEM_BYTES>>>(hbuf, a1, a2, W2, b2, out, N);
}